// round 1
// baseline (speedup 1.0000x reference)
#include <cuda_runtime.h>
#include <cuda_bf16.h>
#include <cstdint>

// Problem constants
#define Bb   16
#define Cc   1024
#define Nn   32
#define Hh   8
#define Dd   128
#define Dhd  16
#define NP   (Bb*Cc)          // 16384 (b,c) pairs
#define QSCALE 0.25f          // Dh^-0.5 = 16^-0.5

// Scratch (device globals — no runtime allocation allowed)
__device__ float g_query[(size_t)NP * Dd];           // 8 MB
__device__ float g_wsum[(size_t)NP * Hh * Dd];       // 64 MB
__device__ float g_asum[(size_t)NP * Hh];            // 512 KB

// ---------------------------------------------------------------------------
// K1: query[p,d] = atom_query[p,:] @ Wq + bq      (32 pairs per block)
// smem: Wq_s[128][132], aq_s[32][132], bq_s[128]  -> 84992 B
// ---------------------------------------------------------------------------
__global__ __launch_bounds__(256) void k_query(const float* __restrict__ aq,
                                               const float* __restrict__ Wq,
                                               const float* __restrict__ bq)
{
    extern __shared__ float sm[];
    float* Wq_s = sm;                  // 128*132
    float* aq_s = Wq_s + 128 * 132;    // 32*132
    float* bq_s = aq_s + 32 * 132;     // 128
    const int t = threadIdx.x;

    #pragma unroll
    for (int j = 0; j < 16; j++) {
        int i4 = t + j * 256;                      // 0..4095 float4s
        int f = i4 >> 5, d4 = i4 & 31;
        float4 v = ((const float4*)Wq)[i4];
        *(float4*)&Wq_s[f * 132 + d4 * 4] = v;
    }
    if (t < 128) bq_s[t] = bq[t];

    const int p0 = blockIdx.x * 32;
    #pragma unroll
    for (int j = 0; j < 4; j++) {
        int i4 = t + j * 256;                      // 0..1023
        int pl = i4 >> 5, e4 = i4 & 31;
        float4 v = ((const float4*)(aq + (size_t)p0 * Dd))[i4];
        *(float4*)&aq_s[pl * 132 + e4 * 4] = v;
    }
    __syncthreads();

    const int w = t >> 5, lane = t & 31;
    const int pl0 = w * 4, d0 = lane * 4;
    float4 acc0 = {0,0,0,0}, acc1 = {0,0,0,0}, acc2 = {0,0,0,0}, acc3 = {0,0,0,0};
    #pragma unroll 4
    for (int f = 0; f < 128; f++) {
        float4 wv = *(float4*)&Wq_s[f * 132 + d0];
        float a0 = aq_s[(pl0 + 0) * 132 + f];
        float a1 = aq_s[(pl0 + 1) * 132 + f];
        float a2 = aq_s[(pl0 + 2) * 132 + f];
        float a3 = aq_s[(pl0 + 3) * 132 + f];
        acc0.x += a0 * wv.x; acc0.y += a0 * wv.y; acc0.z += a0 * wv.z; acc0.w += a0 * wv.w;
        acc1.x += a1 * wv.x; acc1.y += a1 * wv.y; acc1.z += a1 * wv.z; acc1.w += a1 * wv.w;
        acc2.x += a2 * wv.x; acc2.y += a2 * wv.y; acc2.z += a2 * wv.z; acc2.w += a2 * wv.w;
        acc3.x += a3 * wv.x; acc3.y += a3 * wv.y; acc3.z += a3 * wv.z; acc3.w += a3 * wv.w;
    }
    float4 b4 = *(float4*)&bq_s[d0];
    acc0.x += b4.x; acc0.y += b4.y; acc0.z += b4.z; acc0.w += b4.w;
    acc1.x += b4.x; acc1.y += b4.y; acc1.z += b4.z; acc1.w += b4.w;
    acc2.x += b4.x; acc2.y += b4.y; acc2.z += b4.z; acc2.w += b4.w;
    acc3.x += b4.x; acc3.y += b4.y; acc3.z += b4.z; acc3.w += b4.w;
    *(float4*)&g_query[(size_t)(p0 + pl0 + 0) * Dd + d0] = acc0;
    *(float4*)&g_query[(size_t)(p0 + pl0 + 1) * Dd + d0] = acc1;
    *(float4*)&g_query[(size_t)(p0 + pl0 + 2) * Dd + d0] = acc2;
    *(float4*)&g_query[(size_t)(p0 + pl0 + 3) * Dd + d0] = acc3;
}

// ---------------------------------------------------------------------------
// K2: per 8-pair batch: qk, then per pair: gated an -> energy -> softmax
//     (attn out) -> wsum (global).  256 threads.
// smem total = 125056 B
// ---------------------------------------------------------------------------
__global__ __launch_bounds__(256) void k_main(const float* __restrict__ anb,
                                              const float* __restrict__ ldist,
                                              const float* __restrict__ maskp,
                                              const float* __restrict__ Wk,
                                              const float* __restrict__ bk,
                                              const float* __restrict__ Wf,
                                              const float* __restrict__ bf,
                                              float* __restrict__ attn_out)
{
    extern __shared__ float sm[];
    float* Wk_s    = sm;                     // 128*129 = 16512
    float* qk_s    = Wk_s + 128 * 129;       // 8*8*132 = 8448
    float* query_s = qk_s + 8 * 8 * 132;     // 8*132  = 1056
    float* an_s    = query_s + 8 * 132;      // 32*132 = 4224
    float* energy_s= an_s + 32 * 132;        // 32*9   = 288
    float* attn_s  = energy_s + 32 * 9;      // 8*36   = 288
    float* eb_s    = attn_s + 8 * 36;        // 64
    float* Wf_s    = eb_s + 64;              // 128
    float* bf_s    = Wf_s + 128;             // 128
    float* bk_s    = bf_s + 128;             // 128

    const int t = threadIdx.x;
    const int p0 = blockIdx.x * 8;

    // load Wk (pad 129, conflict-free e-major scalar reads later)
    #pragma unroll
    for (int j = 0; j < 16; j++) {
        int i4 = t + j * 256;
        int e = i4 >> 5, d4 = i4 & 31;
        float4 v = ((const float4*)Wk)[i4];
        float* dst = &Wk_s[e * 129 + d4 * 4];
        dst[0] = v.x; dst[1] = v.y; dst[2] = v.z; dst[3] = v.w;
    }
    if (t < 128) { Wf_s[t] = Wf[t]; bf_s[t] = bf[t]; bk_s[t] = bk[t]; }
    {   // query for 8 pairs (1024 floats = 256 float4)
        int pl = t >> 5, e4 = t & 31;
        float4 v = ((const float4*)(g_query + (size_t)p0 * Dd))[t];
        *(float4*)&query_s[pl * 132 + e4 * 4] = v;
    }
    __syncthreads();

    // ---- batched qk: thread owns column e, 4 heads; reuse Wk regs over 8 pairs
    {
        const int e = t & 127, hh = t >> 7;   // hh in {0,1} -> heads hh*4..hh*4+3
        float wkr[4][16];
        #pragma unroll
        for (int h4 = 0; h4 < 4; h4++)
            #pragma unroll
            for (int dd = 0; dd < 16; dd++)
                wkr[h4][dd] = Wk_s[e * 129 + (hh * 4 + h4) * 16 + dd];
        #pragma unroll
        for (int p = 0; p < 8; p++) {
            #pragma unroll
            for (int h4 = 0; h4 < 4; h4++) {
                float acc = 0.f;
                #pragma unroll
                for (int dd4 = 0; dd4 < 4; dd4++) {
                    float4 q4 = *(float4*)&query_s[p * 132 + (hh * 4 + h4) * 16 + dd4 * 4];
                    acc += q4.x * wkr[h4][dd4 * 4 + 0] + q4.y * wkr[h4][dd4 * 4 + 1]
                         + q4.z * wkr[h4][dd4 * 4 + 2] + q4.w * wkr[h4][dd4 * 4 + 3];
                }
                qk_s[(p * 8 + hh * 4 + h4) * 132 + e] = acc * QSCALE;
            }
        }
    }
    // energy bias from bk: eb[p,h] = qscaled . bk
    if (t < 64) {
        int p = t >> 3, h = t & 7;
        float acc = 0.f;
        #pragma unroll
        for (int dd = 0; dd < 16; dd++)
            acc += query_s[p * 132 + h * 16 + dd] * bk_s[h * 16 + dd];
        eb_s[t] = acc * QSCALE;
    }
    __syncthreads();

    const int w = t >> 5, lane = t & 31;

    for (int pl = 0; pl < 8; pl++) {
        const int p = p0 + pl;

        // ---- gated an load: an[n,e] = atom_neighbor * swish(dist*Wf+bf)
        #pragma unroll
        for (int j = 0; j < 4; j++) {
            int i4 = t + j * 256;
            int n = i4 >> 5, e4 = i4 & 31;
            float4 v = ((const float4*)(anb + (size_t)p * Nn * Dd))[i4];
            float dval = __ldg(&ldist[(size_t)p * Nn + n]);
            int e = e4 * 4;
            float x0 = dval * Wf_s[e + 0] + bf_s[e + 0];
            float x1 = dval * Wf_s[e + 1] + bf_s[e + 1];
            float x2 = dval * Wf_s[e + 2] + bf_s[e + 2];
            float x3 = dval * Wf_s[e + 3] + bf_s[e + 3];
            float4 g;
            g.x = v.x * (x0 / (1.f + __expf(-x0)));
            g.y = v.y * (x1 / (1.f + __expf(-x1)));
            g.z = v.z * (x2 / (1.f + __expf(-x2)));
            g.w = v.w * (x3 / (1.f + __expf(-x3)));
            *(float4*)&an_s[n * 132 + e] = g;
        }
        __syncthreads();

        // ---- energy[n,h] = an[n,:] . qk[h,:]   (warp w owns n = 4w..4w+3)
        {
            const int n = w * 4 + (lane >> 3), h = lane & 7;
            const float* anr = &an_s[n * 132];
            const float* qkr = &qk_s[(pl * 8 + h) * 132];
            float acc = 0.f;
            #pragma unroll 8
            for (int e4 = 0; e4 < 32; e4++) {
                float4 a4 = *(float4*)&anr[e4 * 4];
                float4 q4 = *(float4*)&qkr[e4 * 4];
                acc += a4.x * q4.x + a4.y * q4.y + a4.z * q4.z + a4.w * q4.w;
            }
            energy_s[n * 9 + h] = acc + eb_s[pl * 8 + h];
        }
        __syncthreads();

        // ---- softmax over n: warp w = head h, lane = n
        {
            const int h = w, n = lane;
            float e = energy_s[n * 9 + h];
            float m = __ldg(&maskp[(size_t)p * Nn + n]);
            e += (1.f - m) * (-1e9f);
            float vmax = e;
            #pragma unroll
            for (int o = 16; o > 0; o >>= 1) vmax = fmaxf(vmax, __shfl_xor_sync(0xffffffffu, vmax, o));
            float ex = __expf(e - vmax);
            float s = ex;
            #pragma unroll
            for (int o = 16; o > 0; o >>= 1) s += __shfl_xor_sync(0xffffffffu, s, o);
            float at = __fdividef(ex, s);
            if (attn_out) {
                int b = p >> 10, c = p & 1023;
                attn_out[((size_t)(b * Hh + h) * Cc + c) * Nn + n] = at;
            }
            float am = at * m;
            attn_s[h * 36 + n] = am;
            float asum = am;
            #pragma unroll
            for (int o = 16; o > 0; o >>= 1) asum += __shfl_xor_sync(0xffffffffu, asum, o);
            if (n == 0) g_asum[(size_t)p * Hh + h] = asum;
        }
        __syncthreads();

        // ---- wsum[h,e] = sum_n attnm[n] * an[n,e]
        {
            const int eq = w & 3, hq = w >> 2;
            const int e = eq * 32 + (lane & 7) * 4;
            const int h = hq * 4 + (lane >> 3);
            const float* ar = &attn_s[h * 36];
            float4 acc = {0, 0, 0, 0};
            #pragma unroll 8
            for (int n = 0; n < 32; n++) {
                float a = ar[n];
                float4 v = *(float4*)&an_s[n * 132 + e];
                acc.x += a * v.x; acc.y += a * v.y; acc.z += a * v.z; acc.w += a * v.w;
            }
            *(float4*)&g_wsum[((size_t)p * Hh + h) * Dd + e] = acc;
        }
        __syncthreads();
    }
}

// ---------------------------------------------------------------------------
// K3: context[p, h*16+dd] = wsum[p,h,:] @ Wv[:, h*16+dd] + asum*bv + query
// 16 pairs per block. smem = 136192 B
// ---------------------------------------------------------------------------
__global__ __launch_bounds__(256) void k_ctx(const float* __restrict__ Wv,
                                             const float* __restrict__ bv,
                                             float* __restrict__ ctx_out)
{
    extern __shared__ float sm[];
    float* Wv_s   = sm;                    // 128*132
    float* ws_s   = Wv_s + 128 * 132;      // 128 rows (16p*8h) * 132
    float* asum_s = ws_s + 128 * 132;      // 128
    float* bv_s   = asum_s + 128;          // 128

    const int t = threadIdx.x;
    const int p0 = blockIdx.x * 16;

    #pragma unroll
    for (int j = 0; j < 16; j++) {
        int i4 = t + j * 256;
        int e = i4 >> 5, d4 = i4 & 31;
        float4 v = ((const float4*)Wv)[i4];
        *(float4*)&Wv_s[e * 132 + d4 * 4] = v;
    }
    #pragma unroll
    for (int j = 0; j < 16; j++) {
        int i4 = t + j * 256;                       // 4096 float4 = 16 pairs * 8h * 32
        int row = i4 >> 5, e4 = i4 & 31;
        float4 v = ((const float4*)(g_wsum + (size_t)p0 * Hh * Dd))[i4];
        *(float4*)&ws_s[row * 132 + e4 * 4] = v;
    }
    if (t < 128) { asum_s[t] = g_asum[(size_t)p0 * Hh + t]; bv_s[t] = bv[t]; }
    __syncthreads();

    const int w = t >> 5, lane = t & 31;
    const int h = lane >> 2, dd0 = (lane & 3) * 4;
    #pragma unroll
    for (int k = 0; k < 2; k++) {
        const int pl = w * 2 + k;
        const float* wr = &ws_s[(pl * 8 + h) * 132];
        float4 acc = {0, 0, 0, 0};
        #pragma unroll 8
        for (int e = 0; e < 128; e++) {
            float s = wr[e];
            float4 wv = *(float4*)&Wv_s[e * 132 + h * 16 + dd0];
            acc.x += s * wv.x; acc.y += s * wv.y; acc.z += s * wv.z; acc.w += s * wv.w;
        }
        float as = asum_s[pl * 8 + h];
        float4 b4 = *(float4*)&bv_s[h * 16 + dd0];
        float4 q4 = *(const float4*)&g_query[(size_t)(p0 + pl) * Dd + h * 16 + dd0];
        acc.x += as * b4.x + q4.x;
        acc.y += as * b4.y + q4.y;
        acc.z += as * b4.z + q4.z;
        acc.w += as * b4.w + q4.w;
        *(float4*)&ctx_out[(size_t)(p0 + pl) * Dd + h * 16 + dd0] = acc;
    }
}

// ---------------------------------------------------------------------------
extern "C" void kernel_launch(void* const* d_in, const int* in_sizes, int n_in,
                              void* d_out, int out_size)
{
    const float* aq    = (const float*)d_in[0];
    const float* anb   = (const float*)d_in[1];
    const float* ldist = (const float*)d_in[2];
    const float* maskp = (const float*)d_in[3];
    const float* Wq    = (const float*)d_in[4];
    const float* bq    = (const float*)d_in[5];
    const float* Wk    = (const float*)d_in[6];
    const float* bk    = (const float*)d_in[7];
    const float* Wv    = (const float*)d_in[8];
    const float* bv    = (const float*)d_in[9];
    const float* Wf    = (const float*)d_in[10];
    const float* bf    = (const float*)d_in[11];

    float* out = (float*)d_out;
    const size_t attn_elems = (size_t)NP * Hh * Nn;   // 4194304
    const size_t ctx_elems  = (size_t)NP * Dd;        // 2097152
    float* attn_out = nullptr;
    float* ctx_out  = nullptr;
    if ((size_t)out_size >= attn_elems + ctx_elems) { attn_out = out; ctx_out = out + attn_elems; }
    else if ((size_t)out_size == attn_elems)        { attn_out = out; }
    else                                            { ctx_out = out; }

    const int SM1 = (128 * 132 + 32 * 132 + 128) * 4;                         // 84992
    const int SM2 = (128 * 129 + 8 * 8 * 132 + 8 * 132 + 32 * 132 + 32 * 9
                     + 8 * 36 + 64 + 3 * 128) * 4;                            // 125056
    const int SM3 = (128 * 132 + 128 * 132 + 128 + 128) * 4;                  // 136192

    cudaFuncSetAttribute(k_query, cudaFuncAttributeMaxDynamicSharedMemorySize, SM1);
    cudaFuncSetAttribute(k_main,  cudaFuncAttributeMaxDynamicSharedMemorySize, SM2);
    cudaFuncSetAttribute(k_ctx,   cudaFuncAttributeMaxDynamicSharedMemorySize, SM3);

    k_query<<<NP / 32, 256, SM1>>>(aq, Wq, bq);
    k_main<<<NP / 8, 256, SM2>>>(anb, ldist, maskp, Wk, bk, Wf, bf, attn_out);
    if (ctx_out)
        k_ctx<<<NP / 16, 256, SM3>>>(Wv, bv, ctx_out);
}

// round 2
// speedup vs baseline: 2.6218x; 2.6218x over previous
#include <cuda_runtime.h>
#include <cuda_bf16.h>
#include <cstdint>

// Problem constants
#define Bb   16
#define Cc   1024
#define Nn   32
#define Hh   8
#define Dd   128
#define Dhd  16
#define NP   (Bb*Cc)          // 16384 (b,c) pairs
#define QSCALE 0.25f          // Dh^-0.5 = 16^-0.5

// Scratch (device globals — no runtime allocation allowed)
__device__ float g_query[(size_t)NP * Dd];           // 8 MB
__device__ float g_wsum[(size_t)NP * Hh * Dd];       // 64 MB
__device__ float g_asum[(size_t)NP * Hh];            // 512 KB

// ---------------------------------------------------------------------------
// K1: query[p,d] = atom_query[p,:] @ Wq + bq      (32 pairs per block)
// smem: Wq_s[128][132], aq_s[32][132], bq_s[128]  -> 84992 B
// ---------------------------------------------------------------------------
__global__ __launch_bounds__(256) void k_query(const float* __restrict__ aq,
                                               const float* __restrict__ Wq,
                                               const float* __restrict__ bq)
{
    extern __shared__ float sm[];
    float* Wq_s = sm;                  // 128*132
    float* aq_s = Wq_s + 128 * 132;    // 32*132
    float* bq_s = aq_s + 32 * 132;     // 128
    const int t = threadIdx.x;

    #pragma unroll
    for (int j = 0; j < 16; j++) {
        int i4 = t + j * 256;                      // 0..4095 float4s
        int f = i4 >> 5, d4 = i4 & 31;
        float4 v = ((const float4*)Wq)[i4];
        *(float4*)&Wq_s[f * 132 + d4 * 4] = v;
    }
    if (t < 128) bq_s[t] = bq[t];

    const int p0 = blockIdx.x * 32;
    #pragma unroll
    for (int j = 0; j < 4; j++) {
        int i4 = t + j * 256;                      // 0..1023
        int pl = i4 >> 5, e4 = i4 & 31;
        float4 v = ((const float4*)(aq + (size_t)p0 * Dd))[i4];
        *(float4*)&aq_s[pl * 132 + e4 * 4] = v;
    }
    __syncthreads();

    const int w = t >> 5, lane = t & 31;
    const int pl0 = w * 4, d0 = lane * 4;
    float4 acc0 = {0,0,0,0}, acc1 = {0,0,0,0}, acc2 = {0,0,0,0}, acc3 = {0,0,0,0};
    #pragma unroll 4
    for (int f = 0; f < 128; f++) {
        float4 wv = *(float4*)&Wq_s[f * 132 + d0];
        float a0 = aq_s[(pl0 + 0) * 132 + f];
        float a1 = aq_s[(pl0 + 1) * 132 + f];
        float a2 = aq_s[(pl0 + 2) * 132 + f];
        float a3 = aq_s[(pl0 + 3) * 132 + f];
        acc0.x += a0 * wv.x; acc0.y += a0 * wv.y; acc0.z += a0 * wv.z; acc0.w += a0 * wv.w;
        acc1.x += a1 * wv.x; acc1.y += a1 * wv.y; acc1.z += a1 * wv.z; acc1.w += a1 * wv.w;
        acc2.x += a2 * wv.x; acc2.y += a2 * wv.y; acc2.z += a2 * wv.z; acc2.w += a2 * wv.w;
        acc3.x += a3 * wv.x; acc3.y += a3 * wv.y; acc3.z += a3 * wv.z; acc3.w += a3 * wv.w;
    }
    float4 b4 = *(float4*)&bq_s[d0];
    acc0.x += b4.x; acc0.y += b4.y; acc0.z += b4.z; acc0.w += b4.w;
    acc1.x += b4.x; acc1.y += b4.y; acc1.z += b4.z; acc1.w += b4.w;
    acc2.x += b4.x; acc2.y += b4.y; acc2.z += b4.z; acc2.w += b4.w;
    acc3.x += b4.x; acc3.y += b4.y; acc3.z += b4.z; acc3.w += b4.w;
    *(float4*)&g_query[(size_t)(p0 + pl0 + 0) * Dd + d0] = acc0;
    *(float4*)&g_query[(size_t)(p0 + pl0 + 1) * Dd + d0] = acc1;
    *(float4*)&g_query[(size_t)(p0 + pl0 + 2) * Dd + d0] = acc2;
    *(float4*)&g_query[(size_t)(p0 + pl0 + 3) * Dd + d0] = acc3;
}

// ---------------------------------------------------------------------------
// K2: per 8-pair batch: qk (Wk staged in 2 halves into union smem), then per
//     pair: gated an -> energy (broadcast) -> softmax -> wsum (broadcast).
// smem = 18016 floats = 72064 B  -> 3 CTAs/SM
// ---------------------------------------------------------------------------
__global__ __launch_bounds__(256, 3) void k_main(const float* __restrict__ anb,
                                                 const float* __restrict__ ldist,
                                                 const float* __restrict__ maskp,
                                                 const float* __restrict__ Wk,
                                                 const float* __restrict__ bk,
                                                 const float* __restrict__ Wf,
                                                 const float* __restrict__ bf,
                                                 float* __restrict__ attn_out)
{
    extern __shared__ float sm[];
    // persistent
    float* qk_s = sm;                    // 8p*8h*128e = 8192   [(pl*8+h)*128 + e]
    float* eb_s = sm + 8192;             // 64
    float* Wf_s = sm + 8256;             // 128
    float* bf_s = sm + 8384;             // 128
    float* U    = sm + 8512;             // union region (9504 floats)
    // phase 1 view
    float* Wk_s    = U;                  // 128e * 65 = 8320
    float* query_s = U + 8320;           // 8*132 = 1056
    float* bk_s    = U + 9376;           // 128
    // phase 2 view
    float* an_s   = U;                   // 32*132 = 4224
    float* epart  = U + 4224;            // 8w*8h*32n = 2048
    float* attn_s = U + 6272;            // 8*33 = 264

    const int t = threadIdx.x;
    const int p0 = blockIdx.x * 8;

    if (t < 128) { Wf_s[t] = Wf[t]; bf_s[t] = bf[t]; bk_s[t] = bk[t]; }
    {   // query for 8 pairs (1024 floats = 256 float4)
        int pl = t >> 5, e4 = t & 31;
        float4 v = ((const float4*)(g_query + (size_t)p0 * Dd))[t];
        *(float4*)&query_s[pl * 132 + e4 * 4] = v;
    }

    // ---- qk: two half-stages of Wk (d<64 -> heads 0..3, d>=64 -> heads 4..7)
    const int e_col = t & 127, h2 = t >> 7;
    #pragma unroll
    for (int half = 0; half < 2; half++) {
        #pragma unroll
        for (int j = 0; j < 8; j++) {
            int i4 = t + j * 256;                  // 0..2047
            int e = i4 >> 4, d4 = i4 & 15;
            float4 v = ((const float4*)Wk)[e * 32 + half * 16 + d4];
            float* dst = &Wk_s[e * 65 + d4 * 4];
            dst[0] = v.x; dst[1] = v.y; dst[2] = v.z; dst[3] = v.w;
        }
        __syncthreads();
        float wkr[2][16];
        #pragma unroll
        for (int hl = 0; hl < 2; hl++)
            #pragma unroll
            for (int dd = 0; dd < 16; dd++)
                wkr[hl][dd] = Wk_s[e_col * 65 + (h2 * 2 + hl) * 16 + dd];
        #pragma unroll
        for (int p = 0; p < 8; p++) {
            #pragma unroll
            for (int hl = 0; hl < 2; hl++) {
                const int h = half * 4 + h2 * 2 + hl;
                float acc = 0.f;
                #pragma unroll
                for (int d4 = 0; d4 < 4; d4++) {
                    float4 q4 = *(float4*)&query_s[p * 132 + h * 16 + d4 * 4]; // broadcast
                    acc += q4.x * wkr[hl][d4 * 4 + 0] + q4.y * wkr[hl][d4 * 4 + 1]
                         + q4.z * wkr[hl][d4 * 4 + 2] + q4.w * wkr[hl][d4 * 4 + 3];
                }
                qk_s[(p * 8 + h) * 128 + e_col] = acc * QSCALE;
            }
        }
        __syncthreads();
    }
    // energy bias eb[p,h] = scaled q . bk  (query_s/bk_s still valid)
    if (t < 64) {
        int p = t >> 3, h = t & 7;
        float acc = 0.f;
        #pragma unroll
        for (int dd = 0; dd < 16; dd++)
            acc += query_s[p * 132 + h * 16 + dd] * bk_s[h * 16 + dd];
        eb_s[t] = acc * QSCALE;
    }
    __syncthreads();

    const int w = t >> 5, lane = t & 31;

    for (int pl = 0; pl < 8; pl++) {
        const size_t p = (size_t)(p0 + pl);

        // ---- A: gated an: an[n,e] = atom_neighbor * swish(dist*Wf+bf)
        const float4* anp = (const float4*)(anb + p * (Nn * Dd));
        #pragma unroll
        for (int j = 0; j < 4; j++) {
            int i4 = t + j * 256;
            int n = i4 >> 5, e4 = i4 & 31;
            float4 v = anp[i4];
            float dval = __ldg(&ldist[p * Nn + n]);
            int e = e4 * 4;
            float x0 = fmaf(dval, Wf_s[e + 0], bf_s[e + 0]);
            float x1 = fmaf(dval, Wf_s[e + 1], bf_s[e + 1]);
            float x2 = fmaf(dval, Wf_s[e + 2], bf_s[e + 2]);
            float x3 = fmaf(dval, Wf_s[e + 3], bf_s[e + 3]);
            float4 g;
            g.x = v.x * __fdividef(x0, 1.f + __expf(-x0));
            g.y = v.y * __fdividef(x1, 1.f + __expf(-x1));
            g.z = v.z * __fdividef(x2, 1.f + __expf(-x2));
            g.w = v.w * __fdividef(x3, 1.f + __expf(-x3));
            *(float4*)&an_s[n * 132 + e] = g;
        }
        __syncthreads();

        // ---- B: energy partials — warp w owns e-chunk [w*16, w*16+16), lane = n
        {
            float a[16];
            #pragma unroll
            for (int i = 0; i < 4; i++)
                *(float4*)&a[i * 4] = *(float4*)&an_s[lane * 132 + w * 16 + i * 4];
            const float* qkp = &qk_s[pl * 8 * 128 + w * 16];
            #pragma unroll
            for (int h = 0; h < 8; h++) {
                float acc = 0.f;
                #pragma unroll
                for (int i = 0; i < 4; i++) {
                    float4 q4 = *(const float4*)&qkp[h * 128 + i * 4];   // broadcast
                    acc += a[i * 4 + 0] * q4.x + a[i * 4 + 1] * q4.y
                         + a[i * 4 + 2] * q4.z + a[i * 4 + 3] * q4.w;
                }
                epart[(w * 8 + h) * 32 + lane] = acc;
            }
        }
        __syncthreads();

        // ---- C: reduce + softmax over n: warp w = head h, lane = n
        {
            const int h = w, n = lane;
            float en = eb_s[pl * 8 + h];
            #pragma unroll
            for (int wc = 0; wc < 8; wc++) en += epart[(wc * 8 + h) * 32 + n];
            float m = __ldg(&maskp[p * Nn + n]);
            en += (1.f - m) * (-1e9f);
            float vmax = en;
            #pragma unroll
            for (int o = 16; o > 0; o >>= 1) vmax = fmaxf(vmax, __shfl_xor_sync(0xffffffffu, vmax, o));
            float ex = __expf(en - vmax);
            float s = ex;
            #pragma unroll
            for (int o = 16; o > 0; o >>= 1) s += __shfl_xor_sync(0xffffffffu, s, o);
            float at = __fdividef(ex, s);
            if (attn_out) {
                int b = (int)(p >> 10), c = (int)(p & 1023);
                attn_out[((size_t)(b * Hh + h) * Cc + c) * Nn + n] = at;
            }
            float am = at * m;
            attn_s[h * 33 + n] = am;
            float asum = am;
            #pragma unroll
            for (int o = 16; o > 0; o >>= 1) asum += __shfl_xor_sync(0xffffffffu, asum, o);
            if (n == 0) g_asum[p * Hh + h] = asum;
        }
        __syncthreads();

        // ---- D: wsum[h,e] = sum_n attnm[h,n] * an[n,e]; thread = (h-half, e)
        {
            const int e = t & 127, hh = t >> 7;
            const float* abase = &attn_s[hh * 4 * 33];
            float4 acc = {0, 0, 0, 0};
            #pragma unroll 8
            for (int n = 0; n < 32; n++) {
                float av = an_s[n * 132 + e];              // conflict-free
                acc.x = fmaf(abase[      n], av, acc.x);   // broadcasts
                acc.y = fmaf(abase[33  + n], av, acc.y);
                acc.z = fmaf(abase[66  + n], av, acc.z);
                acc.w = fmaf(abase[99  + n], av, acc.w);
            }
            float* wout = &g_wsum[(p * Hh + hh * 4) * Dd + e];
            wout[0] = acc.x; wout[128] = acc.y; wout[256] = acc.z; wout[384] = acc.w;
        }
        __syncthreads();
    }
}

// ---------------------------------------------------------------------------
// K3: context[p, h*16+dd] = wsum[p,h,:] @ Wv[:, h*16+dd] + asum*bv + query
// 8 pairs per block. smem = 25024 floats = 100096 B -> 2 CTAs/SM
// ---------------------------------------------------------------------------
__global__ __launch_bounds__(256, 2) void k_ctx(const float* __restrict__ Wv,
                                                const float* __restrict__ bv,
                                                float* __restrict__ ctx_out)
{
    extern __shared__ float sm[];
    float* Wv_s   = sm;                  // 128*128 = 16384 (no pad needed)
    float* ws_s   = sm + 16384;          // 64 rows (8p*8h) * 132 = 8448
    float* asum_s = sm + 24832;          // 64
    float* bv_s   = sm + 24896;          // 128

    const int t = threadIdx.x;
    const int p0 = blockIdx.x * 8;

    #pragma unroll
    for (int j = 0; j < 16; j++) {
        int i4 = t + j * 256;
        ((float4*)Wv_s)[i4] = ((const float4*)Wv)[i4];
    }
    #pragma unroll
    for (int j = 0; j < 8; j++) {
        int i4 = t + j * 256;                       // 2048 float4 = 8p*8h*32
        int row = i4 >> 5, e4 = i4 & 31;
        float4 v = ((const float4*)(g_wsum + (size_t)p0 * Hh * Dd))[i4];
        *(float4*)&ws_s[row * 132 + e4 * 4] = v;
    }
    if (t < 64)  asum_s[t] = g_asum[(size_t)p0 * Hh + t];
    if (t < 128) bv_s[t] = bv[t];
    __syncthreads();

    const int pl = t >> 5, lane = t & 31;
    const int h = lane >> 2, dd0 = (lane & 3) * 4;
    const float* wr  = &ws_s[(pl * 8 + h) * 132];
    const float* wvp = &Wv_s[h * 16 + dd0];
    float4 acc = {0, 0, 0, 0};
    #pragma unroll 8
    for (int e = 0; e < 128; e++) {
        float s = wr[e];                            // 8 distinct banks, 4-way bcast
        float4 wv = *(const float4*)&wvp[e * 128];
        acc.x = fmaf(s, wv.x, acc.x); acc.y = fmaf(s, wv.y, acc.y);
        acc.z = fmaf(s, wv.z, acc.z); acc.w = fmaf(s, wv.w, acc.w);
    }
    float as = asum_s[pl * 8 + h];
    float4 b4 = *(const float4*)&bv_s[h * 16 + dd0];
    float4 q4 = *(const float4*)&g_query[(size_t)(p0 + pl) * Dd + h * 16 + dd0];
    acc.x += as * b4.x + q4.x;
    acc.y += as * b4.y + q4.y;
    acc.z += as * b4.z + q4.z;
    acc.w += as * b4.w + q4.w;
    *(float4*)&ctx_out[(size_t)(p0 + pl) * Dd + h * 16 + dd0] = acc;
}

// ---------------------------------------------------------------------------
extern "C" void kernel_launch(void* const* d_in, const int* in_sizes, int n_in,
                              void* d_out, int out_size)
{
    const float* aq    = (const float*)d_in[0];
    const float* anb   = (const float*)d_in[1];
    const float* ldist = (const float*)d_in[2];
    const float* maskp = (const float*)d_in[3];
    const float* Wq    = (const float*)d_in[4];
    const float* bq    = (const float*)d_in[5];
    const float* Wk    = (const float*)d_in[6];
    const float* bk    = (const float*)d_in[7];
    const float* Wv    = (const float*)d_in[8];
    const float* bv    = (const float*)d_in[9];
    const float* Wf    = (const float*)d_in[10];
    const float* bf    = (const float*)d_in[11];

    float* out = (float*)d_out;
    const size_t attn_elems = (size_t)NP * Hh * Nn;   // 4194304
    const size_t ctx_elems  = (size_t)NP * Dd;        // 2097152
    float* attn_out = nullptr;
    float* ctx_out  = nullptr;
    if ((size_t)out_size >= attn_elems + ctx_elems) { attn_out = out; ctx_out = out + attn_elems; }
    else if ((size_t)out_size == attn_elems)        { attn_out = out; }
    else                                            { ctx_out = out; }

    const int SM1 = (128 * 132 + 32 * 132 + 128) * 4;   // 84992
    const int SM2 = 18016 * 4;                          // 72064
    const int SM3 = 25024 * 4;                          // 100096

    cudaFuncSetAttribute(k_query, cudaFuncAttributeMaxDynamicSharedMemorySize, SM1);
    cudaFuncSetAttribute(k_main,  cudaFuncAttributeMaxDynamicSharedMemorySize, SM2);
    cudaFuncSetAttribute(k_ctx,   cudaFuncAttributeMaxDynamicSharedMemorySize, SM3);

    k_query<<<NP / 32, 256, SM1>>>(aq, Wq, bq);
    k_main<<<NP / 8, 256, SM2>>>(anb, ldist, maskp, Wk, bk, Wf, bf, attn_out);
    if (ctx_out)
        k_ctx<<<NP / 8, 256, SM3>>>(Wv, bv, ctx_out);
}

// round 3
// speedup vs baseline: 2.8793x; 1.0982x over previous
#include <cuda_runtime.h>
#include <cuda_bf16.h>
#include <cstdint>

// Problem constants
#define Bb   16
#define Cc   1024
#define Nn   32
#define Hh   8
#define Dd   128
#define NP   (Bb*Cc)          // 16384 (b,c) pairs
#define QSCALE 0.25f          // Dh^-0.5 = 16^-0.5

// Scratch (device globals — no runtime allocation allowed)
__device__ float g_query[(size_t)NP * Dd];           // 8 MB
__device__ float g_wsum[(size_t)NP * Hh * Dd];       // 64 MB
__device__ float g_asum[(size_t)NP * Hh];            // 512 KB

// ---- packed fp32x2 helpers (Blackwell FFMA2) -------------------------------
typedef unsigned long long ull;
__device__ __forceinline__ ull fma2(ull a, ull b, ull c) {
    ull d; asm("fma.rn.f32x2 %0, %1, %2, %3;" : "=l"(d) : "l"(a), "l"(b), "l"(c));
    return d;
}
__device__ __forceinline__ ull pk2(float lo, float hi) {
    ull r; asm("mov.b64 %0, {%1, %2};" : "=l"(r) : "f"(lo), "f"(hi)); return r;
}
__device__ __forceinline__ float2 upk2(ull v) {
    float2 r; asm("mov.b64 {%0, %1}, %2;" : "=f"(r.x), "=f"(r.y) : "l"(v)); return r;
}
#define U64(d) __double_as_longlong(d)

// ---------------------------------------------------------------------------
// K1: query[p,d] = atom_query[p,:] @ Wq + bq      (32 pairs per block)
// ---------------------------------------------------------------------------
__global__ __launch_bounds__(256) void k_query(const float* __restrict__ aq,
                                               const float* __restrict__ Wq,
                                               const float* __restrict__ bq)
{
    extern __shared__ float sm[];
    float* Wq_s = sm;                  // 128*132
    float* aq_s = Wq_s + 128 * 132;    // 32*132
    float* bq_s = aq_s + 32 * 132;     // 128
    const int t = threadIdx.x;

    #pragma unroll
    for (int j = 0; j < 16; j++) {
        int i4 = t + j * 256;
        int f = i4 >> 5, d4 = i4 & 31;
        float4 v = ((const float4*)Wq)[i4];
        *(float4*)&Wq_s[f * 132 + d4 * 4] = v;
    }
    if (t < 128) bq_s[t] = bq[t];

    const int p0 = blockIdx.x * 32;
    #pragma unroll
    for (int j = 0; j < 4; j++) {
        int i4 = t + j * 256;
        int pl = i4 >> 5, e4 = i4 & 31;
        float4 v = ((const float4*)(aq + (size_t)p0 * Dd))[i4];
        *(float4*)&aq_s[pl * 132 + e4 * 4] = v;
    }
    __syncthreads();

    const int w = t >> 5, lane = t & 31;
    const int pl0 = w * 4, d0 = lane * 4;
    ull acc[4][2];
    #pragma unroll
    for (int k = 0; k < 4; k++) { acc[k][0] = 0ULL; acc[k][1] = 0ULL; }
    #pragma unroll 4
    for (int f = 0; f < 128; f++) {
        double2 wv = *(double2*)&Wq_s[f * 132 + d0];     // LDS.128
        #pragma unroll
        for (int k = 0; k < 4; k++) {
            float a = aq_s[(pl0 + k) * 132 + f];         // broadcast
            ull a2 = pk2(a, a);
            acc[k][0] = fma2(a2, U64(wv.x), acc[k][0]);
            acc[k][1] = fma2(a2, U64(wv.y), acc[k][1]);
        }
    }
    float4 b4 = *(float4*)&bq_s[d0];
    #pragma unroll
    for (int k = 0; k < 4; k++) {
        float2 lo = upk2(acc[k][0]), hi = upk2(acc[k][1]);
        float4 r = { lo.x + b4.x, lo.y + b4.y, hi.x + b4.z, hi.y + b4.w };
        *(float4*)&g_query[(size_t)(p0 + pl0 + k) * Dd + d0] = r;
    }
}

// ---------------------------------------------------------------------------
// K2: per 8-pair batch: qk (Wk staged in 2 halves, union smem), then per pair:
//     prefetched gated an -> energy (f32x2) -> softmax -> wsum (f32x2).
// smem = 18400 floats = 73600 B  -> 3 CTAs/SM
// ---------------------------------------------------------------------------
__global__ __launch_bounds__(256, 3) void k_main(const float* __restrict__ anb,
                                                 const float* __restrict__ ldist,
                                                 const float* __restrict__ maskp,
                                                 const float* __restrict__ Wk,
                                                 const float* __restrict__ bk,
                                                 const float* __restrict__ Wf,
                                                 const float* __restrict__ bf,
                                                 float* __restrict__ attn_out)
{
    extern __shared__ float sm[];
    // persistent
    float* qk_s = sm;                    // 8p*8h*128e = 8192   [(pl*8+h)*128 + e]
    float* eb_s = sm + 8192;             // 64
    float* Wf_s = sm + 8256;             // 128
    float* bf_s = sm + 8384;             // 128
    float* U    = sm + 8512;             // union (9888 floats)
    // phase 1 view
    float* Wk_s    = U;                  // 128e * 68 = 8704 (half of d staged)
    float* query_s = U + 8704;           // 8*132 = 1056
    float* bk_s    = U + 9760;           // 128
    // phase 2 view
    float* an_s   = U;                   // 32*132 = 4224
    float* epart  = U + 4224;            // 8w*8h*32n = 2048
    float* attn_s = U + 6272;            // 32*12 = 384  [n*12 + h]

    const int t = threadIdx.x;
    const int p0 = blockIdx.x * 8;

    if (t < 128) { Wf_s[t] = Wf[t]; bf_s[t] = bf[t]; bk_s[t] = bk[t]; }
    {   // query for 8 pairs (1024 floats = 256 float4)
        int pl = t >> 5, e4 = t & 31;
        float4 v = ((const float4*)(g_query + (size_t)p0 * Dd))[t];
        *(float4*)&query_s[pl * 132 + e4 * 4] = v;
    }

    // ---- qk: two half-stages of Wk (d<64 -> heads 0..3, d>=64 -> heads 4..7)
    const int e_col = t & 127, h2 = t >> 7;
    #pragma unroll
    for (int half = 0; half < 2; half++) {
        #pragma unroll
        for (int j = 0; j < 8; j++) {
            int i4 = t + j * 256;                  // 0..2047
            int e = i4 >> 4, d4 = i4 & 15;
            float4 v = ((const float4*)Wk)[e * 32 + half * 16 + d4];
            *(float4*)&Wk_s[e * 68 + d4 * 4] = v;
        }
        __syncthreads();
        ull wk2[2][8];
        #pragma unroll
        for (int hl = 0; hl < 2; hl++)
            #pragma unroll
            for (int i = 0; i < 4; i++) {
                double2 w2 = *(double2*)&Wk_s[e_col * 68 + (h2 * 2 + hl) * 16 + i * 4];
                wk2[hl][i * 2 + 0] = U64(w2.x);
                wk2[hl][i * 2 + 1] = U64(w2.y);
            }
        #pragma unroll
        for (int p = 0; p < 8; p++) {
            #pragma unroll
            for (int hl = 0; hl < 2; hl++) {
                const int h = half * 4 + h2 * 2 + hl;
                ull acc2 = 0ULL;
                #pragma unroll
                for (int i = 0; i < 4; i++) {
                    double2 q2 = *(double2*)&query_s[p * 132 + h * 16 + i * 4]; // bcast
                    acc2 = fma2(wk2[hl][i * 2 + 0], U64(q2.x), acc2);
                    acc2 = fma2(wk2[hl][i * 2 + 1], U64(q2.y), acc2);
                }
                float2 a = upk2(acc2);
                qk_s[(p * 8 + h) * 128 + e_col] = (a.x + a.y) * QSCALE;
            }
        }
        __syncthreads();
    }
    // energy bias eb[p,h] = scaled q . bk  (query_s/bk_s still valid)
    if (t < 64) {
        int p = t >> 3, h = t & 7;
        float acc = 0.f;
        #pragma unroll
        for (int dd = 0; dd < 16; dd++)
            acc += query_s[p * 132 + h * 16 + dd] * bk_s[h * 16 + dd];
        eb_s[t] = acc * QSCALE;
    }
    __syncthreads();

    const int w = t >> 5, lane = t & 31;

    // prefetch buffers for pair pl
    float4 pf[4]; float pfd[4]; float pm;
    {
        const float4* anp = (const float4*)(anb + (size_t)p0 * (Nn * Dd));
        #pragma unroll
        for (int j = 0; j < 4; j++) {
            int i4 = t + j * 256;
            pf[j] = anp[i4];
            pfd[j] = __ldg(&ldist[(size_t)p0 * Nn + (i4 >> 5)]);
        }
        pm = __ldg(&maskp[(size_t)p0 * Nn + lane]);
    }

    for (int pl = 0; pl < 8; pl++) {
        const size_t p = (size_t)(p0 + pl);
        const float pm_cur = pm;

        // ---- A: gated an from prefetched regs: an[n,e] = anb * swish(d*Wf+bf)
        #pragma unroll
        for (int j = 0; j < 4; j++) {
            int i4 = t + j * 256;
            int n = i4 >> 5, e4 = i4 & 31;
            float4 v = pf[j];
            float dval = pfd[j];
            int e = e4 * 4;
            float x0 = fmaf(dval, Wf_s[e + 0], bf_s[e + 0]);
            float x1 = fmaf(dval, Wf_s[e + 1], bf_s[e + 1]);
            float x2 = fmaf(dval, Wf_s[e + 2], bf_s[e + 2]);
            float x3 = fmaf(dval, Wf_s[e + 3], bf_s[e + 3]);
            float4 g;
            g.x = v.x * __fdividef(x0, 1.f + __expf(-x0));
            g.y = v.y * __fdividef(x1, 1.f + __expf(-x1));
            g.z = v.z * __fdividef(x2, 1.f + __expf(-x2));
            g.w = v.w * __fdividef(x3, 1.f + __expf(-x3));
            *(float4*)&an_s[n * 132 + e] = g;
        }
        __syncthreads();

        // prefetch next pair while B/C/D run
        if (pl < 7) {
            const float4* anp = (const float4*)(anb + (p + 1) * (Nn * Dd));
            #pragma unroll
            for (int j = 0; j < 4; j++) {
                int i4 = t + j * 256;
                pf[j] = anp[i4];
                pfd[j] = __ldg(&ldist[(p + 1) * Nn + (i4 >> 5)]);
            }
            pm = __ldg(&maskp[(p + 1) * Nn + lane]);
        }

        // ---- B: energy partials — warp w owns e-chunk [w*16,+16), lane = n
        {
            ull a2[8];
            #pragma unroll
            for (int i = 0; i < 4; i++) {
                double2 av = *(double2*)&an_s[lane * 132 + w * 16 + i * 4];
                a2[i * 2 + 0] = U64(av.x);
                a2[i * 2 + 1] = U64(av.y);
            }
            const float* qkp = &qk_s[pl * 8 * 128 + w * 16];
            #pragma unroll
            for (int h = 0; h < 8; h++) {
                ull acc2 = 0ULL;
                #pragma unroll
                for (int i = 0; i < 4; i++) {
                    double2 q2 = *(const double2*)&qkp[h * 128 + i * 4]; // bcast
                    acc2 = fma2(a2[i * 2 + 0], U64(q2.x), acc2);
                    acc2 = fma2(a2[i * 2 + 1], U64(q2.y), acc2);
                }
                float2 a = upk2(acc2);
                epart[(w * 8 + h) * 32 + lane] = a.x + a.y;
            }
        }
        __syncthreads();

        // ---- C: reduce + softmax over n (no max pass): warp w = head, lane = n
        {
            const int h = w, n = lane;
            float en = eb_s[pl * 8 + h];
            #pragma unroll
            for (int wc = 0; wc < 8; wc++) en += epart[(wc * 8 + h) * 32 + n];
            en += (1.f - pm_cur) * (-1e9f);
            float ex = __expf(en);
            float exm = ex * pm_cur;
            float s = ex, smm = exm;
            #pragma unroll
            for (int o = 16; o > 0; o >>= 1) {
                s   += __shfl_xor_sync(0xffffffffu, s, o);
                smm += __shfl_xor_sync(0xffffffffu, smm, o);
            }
            float rinv = __fdividef(1.f, s);
            float at = ex * rinv;
            if (attn_out) {
                int b = (int)(p >> 10), c = (int)(p & 1023);
                attn_out[((size_t)(b * Hh + h) * Cc + c) * Nn + n] = at;
            }
            attn_s[n * 12 + h] = at * pm_cur;
            if (n == 0) g_asum[p * Hh + h] = smm * rinv;
        }
        __syncthreads();

        // ---- D: wsum[h,e] = sum_n attnm[h,n]*an[n,e]; thread = (e, h-half)
        {
            const int e = t & 127, hh = t >> 7;
            ull acc01 = 0ULL, acc23 = 0ULL;
            #pragma unroll 8
            for (int n = 0; n < 32; n++) {
                float av = an_s[n * 132 + e];                    // conflict-free
                ull av2 = pk2(av, av);
                double2 at2 = *(double2*)&attn_s[n * 12 + hh * 4]; // bcast LDS.128
                acc01 = fma2(av2, U64(at2.x), acc01);
                acc23 = fma2(av2, U64(at2.y), acc23);
            }
            float2 a01 = upk2(acc01), a23 = upk2(acc23);
            float* wout = &g_wsum[(p * Hh + hh * 4) * Dd + e];
            wout[0] = a01.x; wout[128] = a01.y; wout[256] = a23.x; wout[384] = a23.y;
        }
        __syncthreads();
    }
}

// ---------------------------------------------------------------------------
// K3: context[p, h*16+dd] = wsum[p,h,:] @ Wv[:, h*16+dd] + asum*bv + query
// 8 pairs per block. smem = 25024 floats = 100096 B -> 2 CTAs/SM
// ---------------------------------------------------------------------------
__global__ __launch_bounds__(256, 2) void k_ctx(const float* __restrict__ Wv,
                                                const float* __restrict__ bv,
                                                float* __restrict__ ctx_out)
{
    extern __shared__ float sm[];
    float* Wv_s   = sm;                  // 128*128 = 16384
    float* ws_s   = sm + 16384;          // 64 rows (8p*8h) * 132 = 8448
    float* asum_s = sm + 24832;          // 64
    float* bv_s   = sm + 24896;          // 128

    const int t = threadIdx.x;
    const int p0 = blockIdx.x * 8;

    #pragma unroll
    for (int j = 0; j < 16; j++) {
        int i4 = t + j * 256;
        ((float4*)Wv_s)[i4] = ((const float4*)Wv)[i4];
    }
    #pragma unroll
    for (int j = 0; j < 8; j++) {
        int i4 = t + j * 256;
        int row = i4 >> 5, e4 = i4 & 31;
        float4 v = ((const float4*)(g_wsum + (size_t)p0 * Hh * Dd))[i4];
        *(float4*)&ws_s[row * 132 + e4 * 4] = v;
    }
    if (t < 64)  asum_s[t] = g_asum[(size_t)p0 * Hh + t];
    if (t < 128) bv_s[t] = bv[t];
    __syncthreads();

    const int pl = t >> 5, lane = t & 31;
    const int h = lane >> 2, dd0 = (lane & 3) * 4;
    const float* wr  = &ws_s[(pl * 8 + h) * 132];
    const float* wvp = &Wv_s[h * 16 + dd0];
    ull acc01 = 0ULL, acc23 = 0ULL;
    #pragma unroll 8
    for (int e = 0; e < 128; e++) {
        float s = wr[e];                           // 8 banks, 4-way bcast
        ull s2 = pk2(s, s);
        double2 wv = *(const double2*)&wvp[e * 128];
        acc01 = fma2(s2, U64(wv.x), acc01);
        acc23 = fma2(s2, U64(wv.y), acc23);
    }
    float as = asum_s[pl * 8 + h];
    float4 b4 = *(const float4*)&bv_s[h * 16 + dd0];
    float4 q4 = *(const float4*)&g_query[(size_t)(p0 + pl) * Dd + h * 16 + dd0];
    float2 a01 = upk2(acc01), a23 = upk2(acc23);
    float4 r;
    r.x = a01.x + as * b4.x + q4.x;
    r.y = a01.y + as * b4.y + q4.y;
    r.z = a23.x + as * b4.z + q4.z;
    r.w = a23.y + as * b4.w + q4.w;
    *(float4*)&ctx_out[(size_t)(p0 + pl) * Dd + h * 16 + dd0] = r;
}

// ---------------------------------------------------------------------------
extern "C" void kernel_launch(void* const* d_in, const int* in_sizes, int n_in,
                              void* d_out, int out_size)
{
    const float* aq    = (const float*)d_in[0];
    const float* anb   = (const float*)d_in[1];
    const float* ldist = (const float*)d_in[2];
    const float* maskp = (const float*)d_in[3];
    const float* Wq    = (const float*)d_in[4];
    const float* bq    = (const float*)d_in[5];
    const float* Wk    = (const float*)d_in[6];
    const float* bk    = (const float*)d_in[7];
    const float* Wv    = (const float*)d_in[8];
    const float* bv    = (const float*)d_in[9];
    const float* Wf    = (const float*)d_in[10];
    const float* bf    = (const float*)d_in[11];

    float* out = (float*)d_out;
    const size_t attn_elems = (size_t)NP * Hh * Nn;   // 4194304
    const size_t ctx_elems  = (size_t)NP * Dd;        // 2097152
    float* attn_out = nullptr;
    float* ctx_out  = nullptr;
    if ((size_t)out_size >= attn_elems + ctx_elems) { attn_out = out; ctx_out = out + attn_elems; }
    else if ((size_t)out_size == attn_elems)        { attn_out = out; }
    else                                            { ctx_out = out; }

    const int SM1 = (128 * 132 + 32 * 132 + 128) * 4;   // 84992
    const int SM2 = 18400 * 4;                          // 73600
    const int SM3 = 25024 * 4;                          // 100096

    cudaFuncSetAttribute(k_query, cudaFuncAttributeMaxDynamicSharedMemorySize, SM1);
    cudaFuncSetAttribute(k_main,  cudaFuncAttributeMaxDynamicSharedMemorySize, SM2);
    cudaFuncSetAttribute(k_ctx,   cudaFuncAttributeMaxDynamicSharedMemorySize, SM3);

    k_query<<<NP / 32, 256, SM1>>>(aq, Wq, bq);
    k_main<<<NP / 8, 256, SM2>>>(anb, ldist, maskp, Wk, bk, Wf, bf, attn_out);
    if (ctx_out)
        k_ctx<<<NP / 8, 256, SM3>>>(Wv, bv, ctx_out);
}